// round 9
// baseline (speedup 1.0000x reference)
#include <cuda_runtime.h>
#include <math.h>

#define VOCAB 50000
#define E 128
#define H 128
#define B 256
#define T 2048

#define HP 132   // padded column count: h1 base = 528 B after h0 -> distinct banks

typedef unsigned long long ull;

// Packed f32x2 FMA (Blackwell)
#define FMA2(d, a, b, c) \
    asm("fma.rn.f32x2 %0, %1, %2, %3;" : "=l"(d) : "l"(a), "l"(b), "l"(c))
#define PACK2(d, lo, hi) \
    asm("mov.b64 %0, {%1, %2};" : "=l"(d) : "f"(lo), "f"(hi))
#define UNPACK2(lo, hi, v) \
    asm("mov.b64 {%0, %1}, %2;" : "=f"(lo), "=f"(hi) : "l"(v))

// Branchless fast tanh: tanh(x) = 1 - 2/(1 + e^{2x}) via MUFU; rel err ~1e-6.
__device__ __forceinline__ float fast_tanh(float x) {
    float e, r;
    asm("ex2.approx.f32 %0, %1;" : "=f"(e) : "f"(x * 2.8853900817779268f));
    asm("rcp.approx.f32 %0, %1;" : "=f"(r) : "f"(e + 1.0f));
    return 1.0f - 2.0f * r;
}
__device__ __forceinline__ float fast_sigmoid(float x) {
    float e, r;
    asm("ex2.approx.f32 %0, %1;" : "=f"(e) : "f"(-x * 1.4426950408889634f));
    asm("rcp.approx.f32 %0, %1;" : "=f"(r) : "f"(e + 1.0f));
    return r;
}

__device__ float g_X0[VOCAB * H];   // emb @ W_ih0 + b0 per vocab id
__device__ int   g_order[B];        // rows sorted by length, descending

// ---------------------------------------------------------------------------
// Kernel B: block 0 rank-sorts lengths, all blocks compute X0.
// ---------------------------------------------------------------------------
__global__ void __launch_bounds__(256)
x0_kernel(const float* __restrict__ emb,
          const float* __restrict__ W_ih,
          const float* __restrict__ b,
          const int* __restrict__ lengths) {
    __shared__ __align__(16) float embs[H];
    __shared__ float part[2 * H];
    __shared__ int s_len[B];

    int tid   = threadIdx.x;
    int half  = tid >> 7;
    int j     = tid & 127;
    int kbase = half * 64;

    if (blockIdx.x == 0) {
        s_len[tid] = lengths[tid];
        __syncthreads();
        int li = s_len[tid];
        int rank = 0;
        for (int jj = 0; jj < B; jj++) {
            int lj = s_len[jj];
            rank += (lj > li) || (lj == li && jj < tid);
        }
        g_order[rank] = tid;
        __syncthreads();
    }

    ull w[32];
    #pragma unroll
    for (int kk = 0; kk < 32; kk++) {
        int k = kbase + 2 * kk;
        PACK2(w[kk], W_ih[k * H + j], W_ih[(k + 1) * H + j]);
    }
    float b0 = b[j];

    for (int r = blockIdx.x; r < VOCAB; r += gridDim.x) {
        if (tid < H) embs[tid] = emb[r * E + tid];
        __syncthreads();
        ull acc = 0;
        #pragma unroll
        for (int i = 0; i < 16; i++) {
            ulonglong2 ev = *(const ulonglong2*)&embs[kbase + 4 * i];
            FMA2(acc, ev.x, w[2 * i], acc);
            FMA2(acc, ev.y, w[2 * i + 1], acc);
        }
        float lo, hi;
        UNPACK2(lo, hi, acc);
        part[tid] = lo + hi;
        __syncthreads();
        if (tid < H) g_X0[r * H + j] = b0 + part[j] + part[H + j];
        __syncthreads();
    }
}

// ---------------------------------------------------------------------------
// Kernel C: persistent per-row RNN, 384 threads = 12 warps, full-k per thread.
//   warps 0-3  (m0): thread j = tid. s0 = W_hh0[:,j] . h0(t)   (k=0..127)
//   warps 4-11 (m12): lane pair shares column j = (w-4)*16 + (l>>1);
//       even lane: s1 = W_ih1[:,j] . h0(t); odd lane: s2 = W_hh1[:,j] . h1(t-1)
//       combine via shfl.xor(1); even lane writes h1(t).
// Superstep t: h0(t+1) = tanh(X0[tok(t+1)] + s0), h1(t) = tanh(b1 + s1 + s2).
// h double-buffered -> 1 barrier/step. Weights: 64 ull regs/thread.
// ---------------------------------------------------------------------------
__global__ void __launch_bounds__(384, 1)
rnn_kernel(const int* __restrict__ x, const int* __restrict__ lengths,
           const float* __restrict__ W_ih, const float* __restrict__ W_hh,
           const float* __restrict__ b, const float* __restrict__ cls_w,
           const float* __restrict__ cls_b, float* __restrict__ out) {
    __shared__ int xrow[T];
    __shared__ __align__(16) float hs[2][2][HP];   // [phase][layer][col]

    int tid = threadIdx.x;
    bool m0 = (tid < 128);

    int j, inlayer, writer;
    const float* wp;
    if (m0) {
        j = tid;  inlayer = 0;  writer = 1;
        wp = W_hh;                       // W_hh layer 0
    } else {
        int u   = tid - 128;
        int l   = u & 31;
        j       = (u >> 5) * 16 + (l >> 1);
        int odd = l & 1;
        inlayer = odd;                   // even reads h0, odd reads h1
        writer  = !odd;                  // even lane writes h1
        wp      = odd ? (W_hh + H * H)   // W_hh layer 1
                      : (W_ih + H * H);  // W_ih layer 1
    }

    // Full-k weight column in registers: 64 ull (128 floats).
    ull w[64];
    #pragma unroll
    for (int kk = 0; kk < 64; kk++)
        PACK2(w[kk], wp[(2 * kk) * H + j], wp[(2 * kk + 1) * H + j]);
    float b1v = b[H + j];

    int row = g_order[blockIdx.x];
    int len = lengths[row];

    // Stage token ids (8 KB).
    for (int i = tid; i < T; i += 384) xrow[i] = x[row * T + i];
    __syncthreads();

    // Prologue: h0(0) = tanh(X0[tok0]) (b0 folded, h_init=0); h1(-1) = 0.
    if (m0) hs[0][0][j] = fast_tanh(g_X0[xrow[0] * H + j]);
    else if (writer) hs[0][1][j] = 0.f;
    float x0cur = 0.f, x0nxt = 0.f;
    if (m0) x0cur = g_X0[xrow[(len > 1) ? 1 : 0] * H + j];
    __syncthreads();

    for (int t = 0; t < len; t++) {
        int p = t & 1;
        const ulonglong2* hin = (const ulonglong2*)&hs[p][inlayer][0];

        // m0 prefetches X0 for superstep t+1 (tok[t+2]).
        if (m0) {
            int tn = t + 2;
            if (tn > len - 1) tn = len - 1;
            x0nxt = g_X0[xrow[tn] * H + j];
        }

        // Full-k dot product, 2 independent FMA2 chains.
        ull acca = 0, accb = 0;
        #pragma unroll
        for (int i = 0; i < 32; i++) {
            ulonglong2 hv = hin[i];
            FMA2(acca, hv.x, w[2 * i],     acca);
            FMA2(accb, hv.y, w[2 * i + 1], accb);
        }
        float la, ha, lb, hb;
        UNPACK2(la, ha, acca);
        UNPACK2(lb, hb, accb);
        float s = (la + ha) + (lb + hb);

        if (m0) {
            hs[p ^ 1][0][j] = fast_tanh(x0cur + s);
        } else {
            float partner = __shfl_xor_sync(0xffffffffu, s, 1);
            if (writer)
                hs[p ^ 1][1][j] = fast_tanh(b1v + s + partner);
        }
        __syncthreads();

        x0cur = x0nxt;
    }

    // ---- classifier: sigmoid(h1_final . cls_w + cls_b) ----
    const float* h1f = hs[len & 1][1];
    if (tid < 32) {
        float v = 0.f;
        #pragma unroll
        for (int m = 0; m < 4; m++) {
            int jj = tid + 32 * m;
            v += h1f[jj] * cls_w[jj];
        }
        #pragma unroll
        for (int off = 16; off; off >>= 1)
            v += __shfl_xor_sync(0xffffffffu, v, off);
        if (tid == 0) out[row] = fast_sigmoid(v + cls_b[0]);
    }
}

// ---------------------------------------------------------------------------
extern "C" void kernel_launch(void* const* d_in, const int* in_sizes, int n_in,
                              void* d_out, int out_size) {
    const int*   x       = (const int*)d_in[0];
    const int*   lengths = (const int*)d_in[1];
    const float* emb     = (const float*)d_in[2];
    const float* W_ih    = (const float*)d_in[3];
    const float* W_hh    = (const float*)d_in[4];
    const float* b       = (const float*)d_in[5];
    const float* cls_w   = (const float*)d_in[6];
    const float* cls_b   = (const float*)d_in[7];
    float*       out     = (float*)d_out;

    x0_kernel<<<1024, 256>>>(emb, W_ih, b, lengths);
    rnn_kernel<<<B, 384>>>(x, lengths, W_ih, W_hh, b, cls_w, cls_b, out);
}

// round 10
// speedup vs baseline: 1.2785x; 1.2785x over previous
#include <cuda_runtime.h>
#include <math.h>

#define VOCAB 50000
#define E 128
#define H 128
#define B 256
#define T 2048

typedef unsigned long long ull;

// Packed f32x2 FMA (Blackwell)
#define FMA2(d, a, b, c) \
    asm("fma.rn.f32x2 %0, %1, %2, %3;" : "=l"(d) : "l"(a), "l"(b), "l"(c))
#define PACK2(d, lo, hi) \
    asm("mov.b64 %0, {%1, %2};" : "=l"(d) : "f"(lo), "f"(hi))
#define UNPACK2(lo, hi, v) \
    asm("mov.b64 {%0, %1}, %2;" : "=f"(lo), "=f"(hi) : "l"(v))

// Device scratch (sanctioned: __device__ globals, no allocation)
__device__ float g_X0[VOCAB * H];   // emb @ W_ih0 + b0 per vocab id
__device__ int   g_order[B];        // rows sorted by length, descending

// ---------------------------------------------------------------------------
// Kernel B: block 0 rank-sorts lengths, all blocks compute X0.
// ---------------------------------------------------------------------------
__global__ void __launch_bounds__(256)
x0_kernel(const float* __restrict__ emb,
          const float* __restrict__ W_ih,
          const float* __restrict__ b,
          const int* __restrict__ lengths) {
    __shared__ __align__(16) float embs[H];
    __shared__ float part[2 * H];
    __shared__ int s_len[B];

    int tid   = threadIdx.x;
    int half  = tid >> 7;
    int j     = tid & 127;
    int kbase = half * 64;

    if (blockIdx.x == 0) {
        s_len[tid] = lengths[tid];
        __syncthreads();
        int li = s_len[tid];
        int rank = 0;
        for (int jj = 0; jj < B; jj++) {
            int lj = s_len[jj];
            rank += (lj > li) || (lj == li && jj < tid);
        }
        g_order[rank] = tid;
        __syncthreads();
    }

    ull w[32];
    #pragma unroll
    for (int kk = 0; kk < 32; kk++) {
        int k = kbase + 2 * kk;
        PACK2(w[kk], W_ih[k * H + j], W_ih[(k + 1) * H + j]);
    }
    float b0 = b[j];

    for (int r = blockIdx.x; r < VOCAB; r += gridDim.x) {
        if (tid < H) embs[tid] = emb[r * E + tid];
        __syncthreads();
        ull acc = 0;
        #pragma unroll
        for (int i = 0; i < 16; i++) {
            ulonglong2 ev = *(const ulonglong2*)&embs[kbase + 4 * i];
            FMA2(acc, ev.x, w[2 * i], acc);
            FMA2(acc, ev.y, w[2 * i + 1], acc);
        }
        float lo, hi;
        UNPACK2(lo, hi, acc);
        part[tid] = lo + hi;
        __syncthreads();
        if (tid < H) g_X0[r * H + j] = b0 + part[j] + part[H + j];
        __syncthreads();
    }
}

// ---------------------------------------------------------------------------
// Kernel C: persistent per-row RNN (R4 structure; acc1+acc2 merged).
// 256 CTAs (one sorted row each, longest first), 256 threads = 8 warps.
// Lane layout: warp w, lane l -> column j = 16*w + (l&15), k-half = l>>4.
// Superstep t computes BOTH h1(t) and h0(t+1) from {h0(t), h1(t-1)}:
//   h1(t)   = tanh(b1 + W_ih1 h0(t) + W_hh1 h1(t-1))   [one merged chain]
//   h0(t+1) = tanh(X0[tok(t+1)] + W_hh0 h0(t))
// Cross-half reduce via shfl.bfly(16); h double-buffered -> 1 barrier/step.
// ---------------------------------------------------------------------------
__global__ void __launch_bounds__(256, 1)
rnn_kernel(const int* __restrict__ x, const int* __restrict__ lengths,
           const float* __restrict__ W_ih, const float* __restrict__ W_hh,
           const float* __restrict__ b, const float* __restrict__ cls_w,
           const float* __restrict__ cls_b, float* __restrict__ out) {
    __shared__ int xrow[T];
    __shared__ __align__(16) float h0s[2][H];
    __shared__ __align__(16) float h1s[2][H];

    int tid   = threadIdx.x;
    int warp  = tid >> 5;
    int lane  = tid & 31;
    int j     = warp * 16 + (lane & 15);
    int half  = lane >> 4;
    int kbase = half * 64;

    int row = g_order[blockIdx.x];
    int len = lengths[row];

    // Pre-packed weight k-pair columns in registers: 3 x 32 ull.
    ull w0p[32], w1p[32], w2p[32];
    #pragma unroll
    for (int kk = 0; kk < 32; kk++) {
        int k = kbase + 2 * kk;
        PACK2(w0p[kk], W_hh[k * H + j],           W_hh[(k + 1) * H + j]);           // W_hh0
        PACK2(w1p[kk], W_ih[H * H + k * H + j],   W_ih[H * H + (k + 1) * H + j]);   // W_ih1
        PACK2(w2p[kk], W_hh[H * H + k * H + j],   W_hh[H * H + (k + 1) * H + j]);   // W_hh1
    }
    float b1v = b[H + j];

    // Stage token ids for this row into smem (8 KB).
    for (int i = tid; i < T; i += 256) xrow[i] = x[row * T + i];
    __syncthreads();

    // Prologue: h0(0) = tanh(X0[tok0]) (b0 folded into X0, h_init = 0); h1(-1)=0.
    if (half == 0) h0s[0][j] = tanhf(g_X0[xrow[0] * H + j]);
    else           h1s[0][j] = 0.f;
    float x0cur = 0.f, x0nxt = 0.f;
    if (half == 0) x0cur = g_X0[xrow[(len > 1) ? 1 : 0] * H + j];
    __syncthreads();

    for (int t = 0; t < len; t++) {
        int p = t & 1;
        const float* hr0 = &h0s[p][kbase];
        const float* hr1 = &h1s[p][kbase];

        // Prefetch X0 for superstep t+1 (needs tok[t+2]).
        if (half == 0) {
            int tn = t + 2;
            if (tn > len - 1) tn = len - 1;
            x0nxt = g_X0[xrow[tn] * H + j];
        }

        // Matmul partials over this k-half (FFMA2-packed).
        // acc0 -> h0-output; acc12 (W_ih1 on h0 + W_hh1 on h1, merged) -> h1.
        ull acc0 = 0, acc12 = 0;
        #pragma unroll
        for (int i = 0; i < 16; i++) {
            ulonglong2 hp = *(const ulonglong2*)(hr0 + 4 * i);
            ulonglong2 gp = *(const ulonglong2*)(hr1 + 4 * i);
            FMA2(acc0,  hp.x, w0p[2 * i],     acc0);
            FMA2(acc12, hp.x, w1p[2 * i],     acc12);
            FMA2(acc12, gp.x, w2p[2 * i],     acc12);
            FMA2(acc0,  hp.y, w0p[2 * i + 1], acc0);
            FMA2(acc12, hp.y, w1p[2 * i + 1], acc12);
            FMA2(acc12, gp.y, w2p[2 * i + 1], acc12);
        }

        // Reduce: packed lanes, then across k-halves (bfly 16).
        float lo, hi, s0, s12;
        UNPACK2(lo, hi, acc0);  s0  = lo + hi;
        UNPACK2(lo, hi, acc12); s12 = lo + hi;
        s0  += __shfl_xor_sync(0xffffffffu, s0,  16);
        s12 += __shfl_xor_sync(0xffffffffu, s12, 16);

        // half 0 produces h0(t+1); half 1 produces h1(t).
        float argv = half ? (b1v + s12) : (x0cur + s0);
        float hv = tanhf(argv);

        // Double-buffered write: no WAR hazard, single barrier per step.
        float* dst = half ? &h1s[p ^ 1][0] : &h0s[p ^ 1][0];
        dst[j] = hv;
        __syncthreads();

        x0cur = x0nxt;
    }

    // ---- classifier: sigmoid(h1_final . cls_w + cls_b) ----
    const float* h1f = h1s[len & 1];
    if (tid < 32) {
        float v = 0.f;
        #pragma unroll
        for (int m = 0; m < 4; m++) {
            int jj = tid + 32 * m;
            v += h1f[jj] * cls_w[jj];
        }
        #pragma unroll
        for (int off = 16; off; off >>= 1)
            v += __shfl_xor_sync(0xffffffffu, v, off);
        if (tid == 0) out[row] = 1.f / (1.f + expf(-(v + cls_b[0])));
    }
}

// ---------------------------------------------------------------------------
extern "C" void kernel_launch(void* const* d_in, const int* in_sizes, int n_in,
                              void* d_out, int out_size) {
    const int*   x       = (const int*)d_in[0];
    const int*   lengths = (const int*)d_in[1];
    const float* emb     = (const float*)d_in[2];
    const float* W_ih    = (const float*)d_in[3];
    const float* W_hh    = (const float*)d_in[4];
    const float* b       = (const float*)d_in[5];
    const float* cls_w   = (const float*)d_in[6];
    const float* cls_b   = (const float*)d_in[7];
    float*       out     = (float*)d_out;

    x0_kernel<<<1024, 256>>>(emb, W_ih, b, lengths);
    rnn_kernel<<<B, 256>>>(x, lengths, W_ih, W_hh, b, cls_w, cls_b, out);
}

// round 11
// speedup vs baseline: 1.2860x; 1.0059x over previous
#include <cuda_runtime.h>
#include <math.h>

#define VOCAB 50000
#define E 128
#define H 128
#define B 256
#define T 2048

typedef unsigned long long ull;

// Packed f32x2 FMA (Blackwell)
#define FMA2(d, a, b, c) \
    asm("fma.rn.f32x2 %0, %1, %2, %3;" : "=l"(d) : "l"(a), "l"(b), "l"(c))
#define PACK2(d, lo, hi) \
    asm("mov.b64 %0, {%1, %2};" : "=l"(d) : "f"(lo), "f"(hi))
#define UNPACK2(lo, hi, v) \
    asm("mov.b64 {%0, %1}, %2;" : "=f"(lo), "=f"(hi) : "l"(v))

// Branchless fast tanh: tanh(x) = 1 - 2/(1 + e^{2x}) via MUFU ex2/rcp.
// rel err ~1e-6 (correct +-1 saturation), safe vs the 1e-3 gate.
__device__ __forceinline__ float fast_tanh(float x) {
    float e, r;
    asm("ex2.approx.f32 %0, %1;" : "=f"(e) : "f"(x * 2.8853900817779268f));
    asm("rcp.approx.f32 %0, %1;" : "=f"(r) : "f"(e + 1.0f));
    return 1.0f - 2.0f * r;
}
__device__ __forceinline__ float fast_sigmoid(float x) {
    float e, r;
    asm("ex2.approx.f32 %0, %1;" : "=f"(e) : "f"(-x * 1.4426950408889634f));
    asm("rcp.approx.f32 %0, %1;" : "=f"(r) : "f"(e + 1.0f));
    return r;
}

// Device scratch (sanctioned: __device__ globals, no allocation)
__device__ float g_X0[VOCAB * H];   // emb @ W_ih0 + b0 per vocab id
__device__ int   g_order[B];        // rows sorted by length, descending

// ---------------------------------------------------------------------------
// Kernel B: block 0 rank-sorts lengths, all blocks compute X0.
// ---------------------------------------------------------------------------
__global__ void __launch_bounds__(256)
x0_kernel(const float* __restrict__ emb,
          const float* __restrict__ W_ih,
          const float* __restrict__ b,
          const int* __restrict__ lengths) {
    __shared__ __align__(16) float embs[H];
    __shared__ float part[2 * H];
    __shared__ int s_len[B];

    int tid   = threadIdx.x;
    int half  = tid >> 7;
    int j     = tid & 127;
    int kbase = half * 64;

    if (blockIdx.x == 0) {
        s_len[tid] = lengths[tid];
        __syncthreads();
        int li = s_len[tid];
        int rank = 0;
        for (int jj = 0; jj < B; jj++) {
            int lj = s_len[jj];
            rank += (lj > li) || (lj == li && jj < tid);
        }
        g_order[rank] = tid;
        __syncthreads();
    }

    ull w[32];
    #pragma unroll
    for (int kk = 0; kk < 32; kk++) {
        int k = kbase + 2 * kk;
        PACK2(w[kk], W_ih[k * H + j], W_ih[(k + 1) * H + j]);
    }
    float b0 = b[j];

    for (int r = blockIdx.x; r < VOCAB; r += gridDim.x) {
        if (tid < H) embs[tid] = emb[r * E + tid];
        __syncthreads();
        ull acc = 0;
        #pragma unroll
        for (int i = 0; i < 16; i++) {
            ulonglong2 ev = *(const ulonglong2*)&embs[kbase + 4 * i];
            FMA2(acc, ev.x, w[2 * i], acc);
            FMA2(acc, ev.y, w[2 * i + 1], acc);
        }
        float lo, hi;
        UNPACK2(lo, hi, acc);
        part[tid] = lo + hi;
        __syncthreads();
        if (tid < H) g_X0[r * H + j] = b0 + part[j] + part[H + j];
        __syncthreads();
    }
}

// ---------------------------------------------------------------------------
// Kernel C: persistent per-row RNN (R4 structure, fast_tanh tail).
// 256 CTAs (one sorted row each, longest first), 256 threads = 8 warps.
// Lane layout: warp w, lane l -> column j = 16*w + (l&15), k-half = l>>4.
// Superstep t computes BOTH h1(t) and h0(t+1) from {h0(t), h1(t-1)}:
//   h1(t)   = tanh(b1 + W_ih1 h0(t) + W_hh1 h1(t-1))
//   h0(t+1) = tanh(X0[tok(t+1)] + W_hh0 h0(t))
// Cross-half reduce via shfl.bfly(16); h double-buffered -> 1 barrier/step.
// ---------------------------------------------------------------------------
__global__ void __launch_bounds__(256, 1)
rnn_kernel(const int* __restrict__ x, const int* __restrict__ lengths,
           const float* __restrict__ W_ih, const float* __restrict__ W_hh,
           const float* __restrict__ b, const float* __restrict__ cls_w,
           const float* __restrict__ cls_b, float* __restrict__ out) {
    __shared__ int xrow[T];
    __shared__ __align__(16) float h0s[2][H];
    __shared__ __align__(16) float h1s[2][H];

    int tid   = threadIdx.x;
    int warp  = tid >> 5;
    int lane  = tid & 31;
    int j     = warp * 16 + (lane & 15);
    int half  = lane >> 4;
    int kbase = half * 64;

    int row = g_order[blockIdx.x];
    int len = lengths[row];

    // Pre-packed weight k-pair columns in registers: 3 x 32 ull.
    ull w0p[32], w1p[32], w2p[32];
    #pragma unroll
    for (int kk = 0; kk < 32; kk++) {
        int k = kbase + 2 * kk;
        PACK2(w0p[kk], W_hh[k * H + j],           W_hh[(k + 1) * H + j]);           // W_hh0
        PACK2(w1p[kk], W_ih[H * H + k * H + j],   W_ih[H * H + (k + 1) * H + j]);   // W_ih1
        PACK2(w2p[kk], W_hh[H * H + k * H + j],   W_hh[H * H + (k + 1) * H + j]);   // W_hh1
    }
    float b1v = b[H + j];

    // Stage token ids for this row into smem (8 KB).
    for (int i = tid; i < T; i += 256) xrow[i] = x[row * T + i];
    __syncthreads();

    // Prologue: h0(0) = tanh(X0[tok0]) (b0 folded into X0, h_init = 0); h1(-1)=0.
    if (half == 0) h0s[0][j] = fast_tanh(g_X0[xrow[0] * H + j]);
    else           h1s[0][j] = 0.f;
    float x0cur = 0.f, x0nxt = 0.f;
    if (half == 0) x0cur = g_X0[xrow[(len > 1) ? 1 : 0] * H + j];
    __syncthreads();

    for (int t = 0; t < len; t++) {
        int p = t & 1;
        const float* hr0 = &h0s[p][kbase];
        const float* hr1 = &h1s[p][kbase];

        // Prefetch X0 for superstep t+1 (needs tok[t+2]).
        if (half == 0) {
            int tn = t + 2;
            if (tn > len - 1) tn = len - 1;
            x0nxt = g_X0[xrow[tn] * H + j];
        }

        // Three matmul partials over this k-half (FFMA2-packed, 3 chains).
        ull acc0 = 0, acc1 = 0, acc2 = 0;
        #pragma unroll
        for (int i = 0; i < 16; i++) {
            ulonglong2 hp = *(const ulonglong2*)(hr0 + 4 * i);
            FMA2(acc0, hp.x, w0p[2 * i],     acc0);
            FMA2(acc0, hp.y, w0p[2 * i + 1], acc0);
            FMA2(acc1, hp.x, w1p[2 * i],     acc1);
            FMA2(acc1, hp.y, w1p[2 * i + 1], acc1);
            ulonglong2 gp = *(const ulonglong2*)(hr1 + 4 * i);
            FMA2(acc2, gp.x, w2p[2 * i],     acc2);
            FMA2(acc2, gp.y, w2p[2 * i + 1], acc2);
        }

        // Reduce: packed lanes, then across k-halves (bfly 16).
        float lo, hi, s0, s1, s2;
        UNPACK2(lo, hi, acc0); s0 = lo + hi;
        UNPACK2(lo, hi, acc1); s1 = lo + hi;
        UNPACK2(lo, hi, acc2); s2 = lo + hi;
        s0 += __shfl_xor_sync(0xffffffffu, s0, 16);
        s1 += __shfl_xor_sync(0xffffffffu, s1, 16);
        s2 += __shfl_xor_sync(0xffffffffu, s2, 16);

        // half 0 produces h0(t+1); half 1 produces h1(t).
        float argv = half ? (b1v + s1 + s2) : (x0cur + s0);
        float hv = fast_tanh(argv);

        // Double-buffered write: no WAR hazard, single barrier per step.
        float* dst = half ? &h1s[p ^ 1][0] : &h0s[p ^ 1][0];
        dst[j] = hv;
        __syncthreads();

        x0cur = x0nxt;
    }

    // ---- classifier: sigmoid(h1_final . cls_w + cls_b) ----
    const float* h1f = h1s[len & 1];
    if (tid < 32) {
        float v = 0.f;
        #pragma unroll
        for (int m = 0; m < 4; m++) {
            int jj = tid + 32 * m;
            v += h1f[jj] * cls_w[jj];
        }
        #pragma unroll
        for (int off = 16; off; off >>= 1)
            v += __shfl_xor_sync(0xffffffffu, v, off);
        if (tid == 0) out[row] = fast_sigmoid(v + cls_b[0]);
    }
}

// ---------------------------------------------------------------------------
extern "C" void kernel_launch(void* const* d_in, const int* in_sizes, int n_in,
                              void* d_out, int out_size) {
    const int*   x       = (const int*)d_in[0];
    const int*   lengths = (const int*)d_in[1];
    const float* emb     = (const float*)d_in[2];
    const float* W_ih    = (const float*)d_in[3];
    const float* W_hh    = (const float*)d_in[4];
    const float* b       = (const float*)d_in[5];
    const float* cls_w   = (const float*)d_in[6];
    const float* cls_b   = (const float*)d_in[7];
    float*       out     = (float*)d_out;

    x0_kernel<<<1024, 256>>>(emb, W_ih, b, lengths);
    rnn_kernel<<<B, 256>>>(x, lengths, W_ih, W_hh, b, cls_w, cls_b, out);
}